// round 2
// baseline (speedup 1.0000x reference)
#include <cuda_runtime.h>
#include <cstdint>

#define TT 512
#define BB 1024
#define CC 64
#define NEGV (-10000.0f)
#define FULLMASK 0xFFFFFFFFu

typedef unsigned long long u64;

// Scratch (no allocations allowed in kernel_launch)
__device__ float g_part[BB];
__device__ float g_E[CC * CC];

// ---- packed f32x2 helpers (Blackwell sm_100+); b64 carried as u64 + "l" ----
static __device__ __forceinline__ u64 fma2(u64 a, u64 b, u64 c) {
    u64 r;
    asm("fma.rn.f32x2 %0, %1, %2, %3;" : "=l"(r) : "l"(a), "l"(b), "l"(c));
    return r;
}
static __device__ __forceinline__ u64 add2(u64 a, u64 b) {
    u64 r;
    asm("add.rn.f32x2 %0, %1, %2;" : "=l"(r) : "l"(a), "l"(b));
    return r;
}
static __device__ __forceinline__ u64 pack2(float lo, float hi) {
    u64 r;
    asm("mov.b64 %0, {%1, %2};" : "=l"(r) : "f"(lo), "f"(hi));
    return r;
}
static __device__ __forceinline__ float hadd2(u64 a) {
    float lo, hi;
    asm("mov.b64 {%0, %1}, %2;" : "=f"(lo), "=f"(hi) : "l"(a));
    return lo + hi;
}

// Precompute E = exp(trans) once (shared by all chains).
__global__ void crf_exp_trans(const float* __restrict__ trans) {
    int i = blockIdx.x * blockDim.x + threadIdx.x;
    if (i < CC * CC) g_E[i] = __expf(trans[i]);
}

// One warp per batch chain. Thread `lane` owns states 2*lane, 2*lane+1.
__global__ void __launch_bounds__(32) crf_chain(
    const float* __restrict__ h,      // (T, B, C)
    const int*   __restrict__ y0,     // (T+1, B)
    const float* __restrict__ mask,   // (T, B)
    const float* __restrict__ trans)  // (C, C)
{
    __shared__ __align__(16) float tr_sh[CC * CC];
    __shared__ __align__(16) u64   p_sh[2][32];

    const int b    = blockIdx.x;
    const int lane = threadIdx.x;
    const int j0   = 2 * lane;
    const int j1   = 2 * lane + 1;

    // trans -> shared (for score gathers + EOS/PAD rows)
    {
        const float4* g4 = (const float4*)trans;
        float4*       s4 = (float4*)tr_sh;
#pragma unroll
        for (int k = 0; k < (CC * CC / 4) / 32; k++)
            s4[lane + 32 * k] = g4[lane + 32 * k];
    }

    // E rows into registers as packed f32x2 pairs: e[k] = (E[j,2k], E[j,2k+1])
    u64 e0[32], e1[32];
    {
        const ulonglong2* ge = (const ulonglong2*)g_E;
#pragma unroll
        for (int k = 0; k < 16; k++) {
            ulonglong2 q0 = ge[j0 * 16 + k];
            ulonglong2 q1 = ge[j1 * 16 + k];
            e0[2 * k] = q0.x; e0[2 * k + 1] = q0.y;
            e1[2 * k] = q1.x; e1[2 * k + 1] = q1.y;
        }
    }

    // Z init: NEG everywhere except SOS(=1)=0.  Pivot M = 0.
    float z0 = (j0 == 1) ? 0.0f : NEGV;
    float z1 = (j1 == 1) ? 0.0f : NEGV;
    float M  = 0.0f;
    p_sh[0][lane] = pack2(__expf(z0 - M), __expf(z1 - M));
    __syncwarp();

    // h prefetch ring: float2 per thread per timestep, depth 4
    const float2* hp   = (const float2*)h;
    const int     HROW = BB * CC / 2;          // 32768 float2 per t
    const int     hoff = b * (CC / 2) + lane;  // b*32 + lane
    float2 hb[4];
#pragma unroll
    for (int k = 0; k < 4; k++) hb[k] = hp[(size_t)k * HROW + hoff];

    float S      = 0.0f;
    int   y_prev = 1;   // y0[0] = SOS
    int   len    = TT;
    bool  done   = false;
    int   buf    = 0;

    for (int w = 0; w < TT && !done; w += 32) {
        // window loads: lane l holds y0[w+1+l] and mask[w+l]
        const int   yN = y0[(w + 1 + lane) * BB + b];
        const float mw = mask[(w + lane) * BB + b];

#pragma unroll 4
        for (int s = 0; s < 32; s++) {
            const int   t = w + s;
            const float m = __shfl_sync(FULLMASK, mw, s);
            if (m == 0.0f) { len = t; done = true; break; }  // mask is monotone
            const int y_next = __shfl_sync(FULLMASK, yN, s);

            // mat-vec: acc_j = sum_i E[j,i] * p[i]   (packed f32x2)
            const ulonglong2* pv = (const ulonglong2*)p_sh[buf];
            u64 a00 = 0, a01 = 0, a10 = 0, a11 = 0;
#pragma unroll
            for (int k = 0; k < 16; k++) {
                ulonglong2 q = pv[k];
                a00 = fma2(e0[2 * k],     q.x, a00);
                a01 = fma2(e0[2 * k + 1], q.y, a01);
                a10 = fma2(e1[2 * k],     q.x, a10);
                a11 = fma2(e1[2 * k + 1], q.y, a11);
            }
            const float acc0 = hadd2(add2(a00, a01));
            const float acc1 = hadd2(add2(a10, a11));

            // consume h(t), prefetch h(t+4)
            const float2 hc = hb[s & 3];
            {
                int tf = t + 4;
                if (tf > TT - 1) tf = TT - 1;
                hb[s & 3] = hp[(size_t)tf * HROW + hoff];
            }

            // Z update (always unmasked here; masked steps exited above)
            z0 = M + __logf(acc0) + hc.x;
            z1 = M + __logf(acc1) + hc.y;

            // score: h[t,b,y_next] via shfl + trans[y_next, y_prev]
            const float hlo = __shfl_sync(FULLMASK, hc.x, y_next >> 1);
            const float hhi = __shfl_sync(FULLMASK, hc.y, y_next >> 1);
            const float hv  = (y_next & 1) ? hhi : hlo;
            const float trv = tr_sh[y_next * CC + y_prev];
            if (t < TT - 1) S += hv + trv;   // emit/tr arrays have T-1 rows
            y_prev = y_next;

            // new pivot = Z[state 3] (thread 1's hi state); compute p, publish
            M = __shfl_sync(FULLMASK, z1, 1);
            p_sh[buf ^ 1][lane] = pack2(__expf(z0 - M), __expf(z1 - M));
            buf ^= 1;
            __syncwarp();
        }
    }

    // final: Zf = logsumexp_j(Z[j] + trans[EOS, j])
    float v0 = z0 + tr_sh[2 * CC + j0];
    float v1 = z1 + tr_sh[2 * CC + j1];
    float mx = fmaxf(v0, v1);
#pragma unroll
    for (int o = 16; o; o >>= 1) mx = fmaxf(mx, __shfl_xor_sync(FULLMASK, mx, o));
    float se = __expf(v0 - mx) + __expf(v1 - mx);
#pragma unroll
    for (int o = 16; o; o >>= 1) se += __shfl_xor_sync(FULLMASK, se, o);
    const float zf = mx + __logf(se);

    // S += trans[PAD, y0[len, b]]
    const int   last = y0[len * BB + b];
    const float Sfin = S + tr_sh[0 * CC + last];

    if (lane == 0) g_part[b] = zf - Sfin;
}

// Deterministic tree reduction of the 1024 per-chain results.
__global__ void crf_reduce(float* __restrict__ out) {
    __shared__ float sh[256];
    const int t = threadIdx.x;
    float s = 0.0f;
#pragma unroll
    for (int k = 0; k < 4; k++) s += g_part[t + 256 * k];
    sh[t] = s;
    __syncthreads();
    for (int o = 128; o; o >>= 1) {
        if (t < o) sh[t] += sh[t + o];
        __syncthreads();
    }
    if (t == 0) out[0] = sh[0] * (1.0f / 1024.0f);
}

extern "C" void kernel_launch(void* const* d_in, const int* in_sizes, int n_in,
                              void* d_out, int out_size) {
    const float* h     = nullptr;
    const int*   y0    = nullptr;
    const float* mask  = nullptr;
    const float* trans = nullptr;
    // identify inputs by (distinct) element counts — robust to ordering
    for (int i = 0; i < n_in; i++) {
        const long n = (long)in_sizes[i];
        if      (n == (long)TT * BB * CC)  h     = (const float*)d_in[i];
        else if (n == (long)(TT + 1) * BB) y0    = (const int*)d_in[i];
        else if (n == (long)TT * BB)       mask  = (const float*)d_in[i];
        else if (n == (long)CC * CC)       trans = (const float*)d_in[i];
    }

    crf_exp_trans<<<(CC * CC + 255) / 256, 256>>>(trans);
    crf_chain<<<BB, 32>>>(h, y0, mask, trans);
    crf_reduce<<<1, 256>>>((float*)d_out);
}

// round 5
// speedup vs baseline: 1.0016x; 1.0016x over previous
#include <cuda_runtime.h>
#include <cstdint>

#define TT 512
#define BB 1024
#define CC 64
#define NEGV (-10000.0f)
#define FULLMASK 0xFFFFFFFFu
#define GRID 148
#define NWARP 8

typedef unsigned long long u64;

// Scratch (no allocations allowed in kernel_launch)
__device__ float g_part[BB];

// ---- packed f32x2 helpers (Blackwell sm_100+); b64 carried as u64 + "l" ----
static __device__ __forceinline__ u64 fma2(u64 a, u64 b, u64 c) {
    u64 r;
    asm("fma.rn.f32x2 %0, %1, %2, %3;" : "=l"(r) : "l"(a), "l"(b), "l"(c));
    return r;
}
static __device__ __forceinline__ u64 add2(u64 a, u64 b) {
    u64 r;
    asm("add.rn.f32x2 %0, %1, %2;" : "=l"(r) : "l"(a), "l"(b));
    return r;
}
static __device__ __forceinline__ u64 pack2(float lo, float hi) {
    u64 r;
    asm("mov.b64 %0, {%1, %2};" : "=l"(r) : "f"(lo), "f"(hi));
    return r;
}
static __device__ __forceinline__ float hadd2(u64 a) {
    float lo, hi;
    asm("mov.b64 {%0, %1}, %2;" : "=f"(lo), "=f"(hi) : "l"(a));
    return lo + hi;
}

// 8 warps/block, warp w of block bl owns chain w*GRID + bl  (7 active warps/SM).
__global__ void __launch_bounds__(NWARP * 32) crf_chain(
    const float* __restrict__ h,      // (T, B, C)
    const int*   __restrict__ y0,     // (T+1, B)
    const float* __restrict__ mask,   // (T, B)
    const float* __restrict__ trans)  // (C, C)
{
    __shared__ __align__(16) float tr_sh[CC * CC];
    __shared__ __align__(16) float E_sh[CC * CC];          // exp(trans), pairwise layout
    __shared__ __align__(16) u64   p_sh[NWARP][2][32];

    const int tid  = threadIdx.x;
    const int lane = tid & 31;
    const int wid  = tid >> 5;

    // cooperative fill: trans -> tr_sh, exp(trans) -> E_sh
    {
        const float4* g4 = (const float4*)trans;
        float4*       t4 = (float4*)tr_sh;
        float4*       e4 = (float4*)E_sh;
#pragma unroll
        for (int k = 0; k < (CC * CC / 4) / (NWARP * 32); k++) {
            const int   idx = tid + NWARP * 32 * k;
            const float4 v  = g4[idx];
            t4[idx] = v;
            float4 e;
            e.x = __expf(v.x); e.y = __expf(v.y);
            e.z = __expf(v.z); e.w = __expf(v.w);
            e4[idx] = e;
        }
    }
    __syncthreads();

    const int chain = wid * GRID + blockIdx.x;
    if (chain >= BB) return;
    const int b  = chain;
    const int j0 = 2 * lane;
    const int j1 = 2 * lane + 1;

    // E rows into registers as packed f32x2 pairs: e[k] = (E[j,2k], E[j,2k+1])
    u64 e0[32], e1[32];
    {
        const ulonglong2* ge = (const ulonglong2*)E_sh;
#pragma unroll
        for (int k = 0; k < 16; k++) {
            ulonglong2 q0 = ge[j0 * 16 + k];
            ulonglong2 q1 = ge[j1 * 16 + k];
            e0[2 * k] = q0.x; e0[2 * k + 1] = q0.y;
            e1[2 * k] = q1.x; e1[2 * k + 1] = q1.y;
        }
    }

    // Z init: NEG everywhere except SOS(=1)=0.  Pivot M = 0.
    float z0 = (j0 == 1) ? 0.0f : NEGV;
    float z1 = (j1 == 1) ? 0.0f : NEGV;
    float M  = 0.0f;
    p_sh[wid][0][lane] = pack2(__expf(z0 - M), __expf(z1 - M));
    __syncwarp();

    // h prefetch ring: float2 per thread per timestep, depth 4
    const float2* hp   = (const float2*)h;
    const int     HROW = BB * CC / 2;          // 32768 float2 per t
    const int     hoff = b * (CC / 2) + lane;  // b*32 + lane
    float2 hb[4];
#pragma unroll
    for (int k = 0; k < 4; k++) hb[k] = hp[(size_t)k * HROW + hoff];

    float S      = 0.0f;
    int   y_prev = 1;   // y0[0] = SOS
    int   len    = TT;
    bool  done   = false;
    int   buf    = 0;

    for (int w = 0; w < TT && !done; w += 32) {
        // window loads: lane l holds y0[w+1+l] and mask[w+l]
        const int   yN = y0[(w + 1 + lane) * BB + b];
        const float mw = mask[(w + lane) * BB + b];

#pragma unroll 4
        for (int s = 0; s < 32; s++) {
            const int   t = w + s;
            const float m = __shfl_sync(FULLMASK, mw, s);
            if (m == 0.0f) { len = t; done = true; break; }  // mask is monotone
            const int y_next = __shfl_sync(FULLMASK, yN, s);

            // mat-vec: acc_j = sum_i E[j,i] * p[i]  (packed f32x2, 4 chains/row)
            const ulonglong2* pv = (const ulonglong2*)p_sh[wid][buf];
            u64 a0[4] = {0, 0, 0, 0};
            u64 a1[4] = {0, 0, 0, 0};
#pragma unroll
            for (int k = 0; k < 16; k++) {
                ulonglong2 q = pv[k];
                const int  c = 2 * (k & 1);
                a0[c]     = fma2(e0[2 * k],     q.x, a0[c]);
                a0[c + 1] = fma2(e0[2 * k + 1], q.y, a0[c + 1]);
                a1[c]     = fma2(e1[2 * k],     q.x, a1[c]);
                a1[c + 1] = fma2(e1[2 * k + 1], q.y, a1[c + 1]);
            }
            const float acc0 = hadd2(add2(add2(a0[0], a0[1]), add2(a0[2], a0[3])));
            const float acc1 = hadd2(add2(add2(a1[0], a1[1]), add2(a1[2], a1[3])));

            // consume h(t), prefetch h(t+4)
            const float2 hc = hb[s & 3];
            {
                int tf = t + 4;
                if (tf > TT - 1) tf = TT - 1;
                hb[s & 3] = hp[(size_t)tf * HROW + hoff];
            }

            // Z update (masked steps exited above)
            z0 = M + __logf(acc0) + hc.x;
            z1 = M + __logf(acc1) + hc.y;

            // score: h[t,b,y_next] via shfl + trans[y_next, y_prev]
            const float hlo = __shfl_sync(FULLMASK, hc.x, y_next >> 1);
            const float hhi = __shfl_sync(FULLMASK, hc.y, y_next >> 1);
            const float hv  = (y_next & 1) ? hhi : hlo;
            const float trv = tr_sh[y_next * CC + y_prev];
            if (t < TT - 1) S += hv + trv;   // emit/tr arrays have T-1 rows
            y_prev = y_next;

            // new pivot = Z[state 3] (thread 1's hi state); compute p, publish
            M = __shfl_sync(FULLMASK, z1, 1);
            p_sh[wid][buf ^ 1][lane] = pack2(__expf(z0 - M), __expf(z1 - M));
            buf ^= 1;
            __syncwarp();
        }
    }

    // final: Zf = logsumexp_j(Z[j] + trans[EOS, j])
    float v0 = z0 + tr_sh[2 * CC + j0];
    float v1 = z1 + tr_sh[2 * CC + j1];
    float mx = fmaxf(v0, v1);
#pragma unroll
    for (int o = 16; o; o >>= 1) mx = fmaxf(mx, __shfl_xor_sync(FULLMASK, mx, o));
    float se = __expf(v0 - mx) + __expf(v1 - mx);
#pragma unroll
    for (int o = 16; o; o >>= 1) se += __shfl_xor_sync(FULLMASK, se, o);
    const float zf = mx + __logf(se);

    // S += trans[PAD, y0[len, b]]
    const int   last = y0[len * BB + b];
    const float Sfin = S + tr_sh[0 * CC + last];

    if (lane == 0) g_part[b] = zf - Sfin;
}

// Deterministic tree reduction of the 1024 per-chain results.
__global__ void crf_reduce(float* __restrict__ out) {
    __shared__ float sh[256];
    const int t = threadIdx.x;
    float s = 0.0f;
#pragma unroll
    for (int k = 0; k < 4; k++) s += g_part[t + 256 * k];
    sh[t] = s;
    __syncthreads();
    for (int o = 128; o; o >>= 1) {
        if (t < o) sh[t] += sh[t + o];
        __syncthreads();
    }
    if (t == 0) out[0] = sh[0] * (1.0f / 1024.0f);
}

extern "C" void kernel_launch(void* const* d_in, const int* in_sizes, int n_in,
                              void* d_out, int out_size) {
    const float* h     = nullptr;
    const int*   y0    = nullptr;
    const float* mask  = nullptr;
    const float* trans = nullptr;
    // identify inputs by (distinct) element counts — robust to ordering
    for (int i = 0; i < n_in; i++) {
        const long n = (long)in_sizes[i];
        if      (n == (long)TT * BB * CC)  h     = (const float*)d_in[i];
        else if (n == (long)(TT + 1) * BB) y0    = (const int*)d_in[i];
        else if (n == (long)TT * BB)       mask  = (const float*)d_in[i];
        else if (n == (long)CC * CC)       trans = (const float*)d_in[i];
    }

    crf_chain<<<GRID, NWARP * 32>>>(h, y0, mask, trans);
    crf_reduce<<<1, 256>>>((float*)d_out);
}